// round 10
// baseline (speedup 1.0000x reference)
#include <cuda_runtime.h>
#include <stdint.h>

#define KEHALF   7.199822675975274f
#define CUTOFF   10.0f
#define L2E      1.4426950408889634f
#define ZMAX     94
#define LUT_REP  32
#define NTHREADS 1024
#define CAP_E    (1 << 22)          // 4.19M edges of scratch

// per-atom z-index bytes (Z-1), built by prep kernel
__device__ __align__(16) uint8_t g_ztab[131072];
// per-edge byte: (Zi-1)+(Zj-1), built by kernel A
__device__ __align__(16) uint8_t g_wsum[CAP_E];

__device__ __forceinline__ float softplus_f(float x) {
    return (x > 20.0f) ? x : log1pf(__expf(x));
}

__global__ void k_prep(const float* __restrict__ Z, int N,
                       float* __restrict__ y, int M) {
    int i = blockIdx.x * blockDim.x + threadIdx.x;
    if (i < M) y[i] = 0.0f;
    if (i < N && i < 131072) g_ztab[i] = (uint8_t)((int)(Z[i] + 0.5f) - 1);
}

// ---------------- Kernel A: gather-only pass -------------------------------
// wsum[e] = ztab[ii[e]] + ztab[jj[e]]  (byte), 8 edges per thread-iteration.
__global__ __launch_bounds__(NTHREADS, 1) void k_gather(
    const int* __restrict__ ii, const int* __restrict__ jj, int N, int E)
{
    extern __shared__ __align__(16) uint8_t ztab[];
    int tid = threadIdx.x;

    {   // stage byte table into smem
        const int4* src = (const int4*)g_ztab;
        int4*       dst = (int4*)ztab;
        int n16 = N >> 4;
        for (int k = tid; k < n16; k += blockDim.x) dst[k] = src[k];
        for (int k = (n16 << 4) + tid; k < N; k += blockDim.x) ztab[k] = g_ztab[k];
    }
    __syncthreads();

    int E8     = E & ~7;
    int Ecap   = (E8 < CAP_E) ? E8 : CAP_E;
    int stride = gridDim.x * blockDim.x * 8;

    for (int e = (blockIdx.x * blockDim.x + tid) * 8; e < Ecap; e += stride) {
        int4 iva = __ldcs((const int4*)(ii + e));
        int4 ivb = __ldcs((const int4*)(ii + e + 4));
        int4 jva = __ldcs((const int4*)(jj + e));
        int4 jvb = __ldcs((const int4*)(jj + e + 4));

        uint32_t w0 =  (uint32_t)(ztab[iva.x] + ztab[jva.x])
                    | ((uint32_t)(ztab[iva.y] + ztab[jva.y]) << 8)
                    | ((uint32_t)(ztab[iva.z] + ztab[jva.z]) << 16)
                    | ((uint32_t)(ztab[iva.w] + ztab[jva.w]) << 24);
        uint32_t w1 =  (uint32_t)(ztab[ivb.x] + ztab[jvb.x])
                    | ((uint32_t)(ztab[ivb.y] + ztab[jvb.y]) << 8)
                    | ((uint32_t)(ztab[ivb.z] + ztab[jvb.z]) << 16)
                    | ((uint32_t)(ztab[ivb.w] + ztab[jvb.w]) << 24);

        *(uint2*)(g_wsum + e) = make_uint2(w0, w1);
    }

    // tail bytes (E8..E) and any overflow region are handled in kernel B.
    if (blockIdx.x == 0) {
        for (int e = E8 + tid; e < E && e < CAP_E; e += blockDim.x)
            g_wsum[e] = (uint8_t)(ztab[ii[e]] + ztab[jj[e]]);
    }
}

// ---------------- Kernel B: stream + test + sparse energy ------------------
// cf layout: [0..3]=b, [4..7]=c, [8]=thr, [9]=wthr2 (conservative, squared)
__device__ __forceinline__ void survivor_edge(
    float s, int e,
    const int* __restrict__ ii, const int* __restrict__ jj,
    const int* __restrict__ im,
    const float* __restrict__ cf, const float* __restrict__ zlut,
    float* bins, int lane)
{
    int i  = __ldg(ii + e);
    int j  = __ldg(jj + e);
    int zi = g_ztab[i];
    int zj = g_ztab[j];
    float zsum = zlut[zi * LUT_REP + lane] + zlut[zj * LUT_REP + lane];
    float rs = rsqrtf(s);
    float d  = s * rs;
    float t  = zsum * d;
    if (t < cf[8] && d < CUTOFF) {   // exact test (beyond thr: exp2 -> 0.0f)
        float f = cf[4] * exp2f(-cf[0] * t) + cf[5] * exp2f(-cf[1] * t)
                + cf[6] * exp2f(-cf[2] * t) + cf[7] * exp2f(-cf[3] * t);
        float u  = d * (1.0f / CUTOFF);
        float u3 = u * u * u;
        float p  = fmaf(-6.0f, u, 15.0f);
        p        = fmaf(p, u, -10.0f);
        float fc = fmaf(u3, p, 1.0f);
        float Zi = (float)(zi + 1), Zj = (float)(zj + 1);
        float ee = KEHALF * f * fc * Zi * Zj * rs;
        if (ee != 0.0f) atomicAdd(&bins[__ldg(im + i)], ee);
    }
}

__global__ __launch_bounds__(NTHREADS, 2) void k_energy(
    const float* __restrict__ r,
    const int*   __restrict__ ii,
    const int*   __restrict__ jj,
    const int*   __restrict__ im,
    const float* __restrict__ adiv,
    const float* __restrict__ apow,
    const float* __restrict__ av,
    const float* __restrict__ cv,
    int E, float* __restrict__ y, int M)
{
    extern __shared__ __align__(16) char smem_raw[];
    float* bins = (float*)smem_raw;      // M floats
    float* cf   = bins + M;              // 16 floats
    float* zlut = cf + 16;               // ZMAX*32 floats (12KB)

    int tid  = threadIdx.x;
    int lane = tid & 31;

    for (int b = tid; b < M; b += blockDim.x) bins[b] = 0.0f;

    if (tid == 0) {
        float sp_adiv = softplus_f(adiv[0]);
        float a0 = softplus_f(av[0]), a1 = softplus_f(av[1]);
        float a2 = softplus_f(av[2]), a3 = softplus_f(av[3]);
        float c0 = softplus_f(cv[0]), c1 = softplus_f(cv[1]);
        float c2 = softplus_f(cv[2]), c3 = softplus_f(cv[3]);
        float cinv = 1.0f / (fabsf(c0) + fabsf(c1) + fabsf(c2) + fabsf(c3));
        float b0 = a0 * sp_adiv * L2E, b1 = a1 * sp_adiv * L2E;
        float b2 = a2 * sp_adiv * L2E, b3 = a3 * sp_adiv * L2E;
        cf[0] = b0; cf[1] = b1; cf[2] = b2; cf[3] = b3;
        cf[4] = c0 * cinv; cf[5] = c1 * cinv; cf[6] = c2 * cinv; cf[7] = c3 * cinv;
        float bmin = fminf(fminf(b0, b1), fminf(b2, b3));
        float thr  = 151.0f / bmin;  // t >= thr => every exp2 term is exactly 0.0f
        cf[8] = thr;
        // Conservative pre-test threshold (z >= Z requires p >= 1):
        float p = softplus_f(apow[0]);
        cf[9] = (p >= 1.0f) ? thr * thr : 3.0e38f;  // else every edge -> slow path
    }

    {   // bank-replicated z-LUT (conflict-free)
        float spw = softplus_f(apow[0]);
        for (int k = tid; k < ZMAX * LUT_REP; k += blockDim.x) {
            int zi = k / LUT_REP;
            zlut[k] = exp2f(spw * log2f((float)(zi + 1)));
        }
    }
    __syncthreads();

    float wthr2 = cf[9];

    int E4     = E & ~3;
    int Ecap   = (E4 < CAP_E) ? E4 : CAP_E;
    int stride = gridDim.x * blockDim.x * 4;
    const float4* rv = (const float4*)r;

    for (int e = (blockIdx.x * blockDim.x + tid) * 4; e < Ecap; e += stride) {
        int fi = (e >> 2) * 3;
        float4 p0 = __ldcs(rv + fi + 0);
        float4 p1 = __ldcs(rv + fi + 1);
        float4 p2 = __ldcs(rv + fi + 2);
        uint32_t w4 = __ldcs((const uint32_t*)(g_wsum + e));

        float fx[12] = {p0.x, p0.y, p0.z, p0.w,
                        p1.x, p1.y, p1.z, p1.w,
                        p2.x, p2.y, p2.z, p2.w};

        #pragma unroll
        for (int k = 0; k < 4; k++) {
            float rx = fx[3 * k], ry = fx[3 * k + 1], rz = fx[3 * k + 2];
            float s  = fmaf(rx, rx, fmaf(ry, ry, rz * rz));     // d^2
            float wf = (float)((w4 >> (8 * k)) & 255u) + 2.0f;  // >= Zi+Zj
            // survivor => (Zi+Zj)*d < thr  (since z >= Z)  => wf^2*s < thr^2
            if (wf * wf * s < wthr2 && s < CUTOFF * CUTOFF)     // ~1% taken
                survivor_edge(s, e + k, ii, jj, im, cf, zlut, bins, lane);
        }
    }

    // tail (E%4) + any edges beyond scratch capacity: exact path from gmem
    if (blockIdx.x == 0) {
        int start = (E4 < CAP_E) ? E4 : CAP_E & ~3;
        for (int e = start + tid; e < E; e += blockDim.x) {
            float rx = r[3 * e], ry = r[3 * e + 1], rz = r[3 * e + 2];
            float s  = fmaf(rx, rx, fmaf(ry, ry, rz * rz));
            survivor_edge(s, e, ii, jj, im, cf, zlut, bins, lane);
        }
    }

    __syncthreads();
    for (int b = tid; b < M; b += blockDim.x) {
        float v = bins[b];
        if (v != 0.0f) atomicAdd(&y[b], v);
    }
}

extern "C" void kernel_launch(void* const* d_in, const int* in_sizes, int n_in,
                              void* d_out, int out_size) {
    const float* Z    = (const float*)d_in[0];
    const float* r    = (const float*)d_in[1];
    const int*   ii   = (const int*)  d_in[2];
    const int*   jj   = (const int*)  d_in[3];
    const int*   im   = (const int*)  d_in[4];
    const float* adiv = (const float*)d_in[5];
    const float* apow = (const float*)d_in[6];
    const float* av   = (const float*)d_in[7];
    const float* cv   = (const float*)d_in[8];

    int N = in_sizes[0];
    int E = in_sizes[2];
    int M = out_size;
    float* y = (float*)d_out;

    int prep_n = (N > M ? N : M);
    k_prep<<<(prep_n + 255) / 256, 256>>>(Z, N, y, M);

    int sm_count = 148;
    cudaDeviceGetAttribute(&sm_count, cudaDevAttrMultiProcessorCount, 0);

    // Kernel A: gather-only (smem = ztab bytes)
    size_t smem_a = (size_t)N + 16;
    cudaFuncSetAttribute(k_gather,
                         cudaFuncAttributeMaxDynamicSharedMemorySize, (int)smem_a);
    k_gather<<<sm_count, NTHREADS, smem_a>>>(ii, jj, N, E);

    // Kernel B: stream + sparse energy (smem = bins + cf + zlut ~ 16KB)
    size_t smem_b = (size_t)M * 4 + 16 * 4 + (size_t)ZMAX * LUT_REP * 4;
    cudaFuncSetAttribute(k_energy,
                         cudaFuncAttributeMaxDynamicSharedMemorySize, (int)smem_b);
    k_energy<<<2 * sm_count, NTHREADS, smem_b>>>(
        r, ii, jj, im, adiv, apow, av, cv, E, y, M);
}